// round 15
// baseline (speedup 1.0000x reference)
#include <cuda_runtime.h>
#include <cuda_bf16.h>
#include <mma.h>
#include <stdint.h>

using namespace nvcuda;

// Loihi CUBA constants
#define AI 0.75f
#define AV 0.96875f
#define TH 100.0f

__device__ __forceinline__ void add2(unsigned long long& a, unsigned long long b) {
    asm("add.rn.f32x2 %0, %0, %1;" : "+l"(a) : "l"(b));
}
__device__ __forceinline__ float2 u64f2(unsigned long long v) {
    float2 f; asm("mov.b64 {%0, %1}, %2;" : "=f"(f.x), "=f"(f.y) : "l"(v)); return f;
}

// ---------------------------------------------------------------------------
// Buffers (bit k of word j = spike at t = j*32+k; all streams pre-delayed)
// FC channel order is REMAPPED: c_new = px*32 + o  (px = h*10+w of conv3).
// g_wh columns and g_sb words both use c_new, so the FC GEMM is consistent.
// ---------------------------------------------------------------------------
__device__ uint32_t g_s0[16 * 2  * 40 * 40 * 4];
__device__ uint32_t g_s3[16 * 16 * 20 * 20 * 4];
__device__ uint32_t g_sb[16 * 128 * 100];           // c_new-major words per (n,t)
__device__ uint8_t  g_cp1[16 * 22 * 22 * 128];      // pool1 out, c-major bytes (padded)
__device__ uint16_t g_cp2[16 * 12 * 12 * 128];      // pool2 out, c-major u16 (padded)
__device__ __nv_bfloat16 g_wh[3 * 512 * 3200];      // FC W bf16 splits, c_new cols
__device__ float    g_dp2[2 * 16 * 512 * 128];      // fc partials (2 c-halves)

// ---------------------------------------------------------------------------
// K0: pack raw float spikes -> bit words
// ---------------------------------------------------------------------------
__global__ void k_pack(const float* __restrict__ sp) {
    int idx = blockIdx.x * blockDim.x + threadIdx.x;
    const float4* p = (const float4*)(sp + (size_t)idx * 128);
    uint32_t w[4];
#pragma unroll
    for (int j = 0; j < 4; j++) {
        uint32_t b = 0;
#pragma unroll
        for (int q = 0; q < 8; q++) {
            float4 v = p[j * 8 + q];
            b |= (v.x > 0.5f ? 1u : 0u) << (q * 4 + 0);
            b |= (v.y > 0.5f ? 1u : 0u) << (q * 4 + 1);
            b |= (v.z > 0.5f ? 1u : 0u) << (q * 4 + 2);
            b |= (v.w > 0.5f ? 1u : 0u) << (q * 4 + 3);
        }
        w[j] = b;
    }
    *((uint4*)&g_s0[(size_t)idx * 4]) = make_uint4(w[0], w[1], w[2], w[3]);
}

// ---------------------------------------------------------------------------
// K_wsplit: FC W fp32 -> 3 bf16 splits, columns in c_new order.
// thread i = (o, pair pr): c_new = 2pr, 2pr+1; gathers W[o][c_ref],
// c_ref = (c_new & 31) * 100 + (c_new >> 5).
// ---------------------------------------------------------------------------
__global__ void k_wsplit(const float* __restrict__ W) {
    int i = blockIdx.x * blockDim.x + threadIdx.x;   // 819200
    int o = i / 1600, pr = i % 1600;
    int cn0 = 2 * pr, cn1 = 2 * pr + 1;
    const float* wrow = W + (size_t)o * 3200;
    float a = wrow[(cn0 & 31) * 100 + (cn0 >> 5)];
    float b = wrow[(cn1 & 31) * 100 + (cn1 >> 5)];
    __nv_bfloat16 ha = __float2bfloat16(a), hb = __float2bfloat16(b);
    float ra = a - __bfloat162float(ha), rb = b - __bfloat162float(hb);
    __nv_bfloat16 ma = __float2bfloat16(ra), mb = __float2bfloat16(rb);
    float sa = ra - __bfloat162float(ma), sb = rb - __bfloat162float(mb);
    __nv_bfloat16 la = __float2bfloat16(sa), lb = __float2bfloat16(sb);
    uint32_t* g = (uint32_t*)g_wh;
    uint16_t uha = *(uint16_t*)&ha, uhb = *(uint16_t*)&hb;
    uint16_t uma = *(uint16_t*)&ma, umb = *(uint16_t*)&mb;
    uint16_t ula = *(uint16_t*)&la, ulb = *(uint16_t*)&lb;
    g[i]              = (uint32_t)uha | ((uint32_t)uhb << 16);
    g[819200 + i]     = (uint32_t)uma | ((uint32_t)umb << 16);
    g[2 * 819200 + i] = (uint32_t)ula | ((uint32_t)ulb << 16);
}

// ---------------------------------------------------------------------------
// K_c1p: FUSED conv1 + LIF + delay + 2x2 pool + LIF + delay + c-major
// transpose -> g_cp1. Block = (n, ph), 640 thr. (R14, proven)
// ---------------------------------------------------------------------------
__global__ void __launch_bounds__(640) k_c1p(const float* __restrict__ cw,
                                             const float* __restrict__ pws) {
    __shared__ uint32_t sh[2 * 4 * 42 * 4];
    __shared__ uint32_t sd[2 * 40 * 8 * 4];
    __shared__ uint32_t sp[8 * 20 * 4];
    int b = blockIdx.x;
    int n = b / 20, ph = b % 20;
    int tid = threadIdx.x;

    for (int i = tid; i < 2 * 4 * 42 * 4; i += 640) {
        int j = i & 3;
        int t2 = i >> 2;
        int wx = t2 % 42;
        int t3 = t2 / 42;
        int row = t3 % 4;
        int c = t3 / 4;
        int hh = 2 * ph - 1 + row, ws = wx - 1;
        uint32_t v = 0;
        if (hh >= 0 && hh < 40 && ws >= 0 && ws < 40)
            v = g_s0[(((n * 2 + c) * 40 + hh) * 40 + ws) * 4 + j];
        sh[((c * 4 + row) * 42 + wx) * 4 + j] = v;
    }
    __syncthreads();

    {   // conv phase: thread = (r, w, o)
        int r = tid / 320;
        int rt = tid % 320;
        int w = rt % 40, o = rt / 40;
        float wg[18];
#pragma unroll
        for (int i = 0; i < 18; i++) wg[i] = cw[o * 18 + i] * 20.0f;

        float u = 0.f, v = 0.f;
        uint32_t ow[4];
#pragma unroll
        for (int j = 0; j < 4; j++) {
            float acc[32];
#pragma unroll
            for (int k = 0; k < 32; k++) acc[k] = 0.f;
#pragma unroll
            for (int c = 0; c < 2; c++)
#pragma unroll
            for (int dy = 0; dy < 3; dy++)
#pragma unroll
            for (int dx = 0; dx < 3; dx++) {
                uint32_t wd = sh[((c * 4 + (r + dy)) * 42 + (w + dx)) * 4 + j];
                float wt = wg[c * 9 + dy * 3 + dx];
#pragma unroll
                for (int k = 0; k < 32; k++)
                    if (wd & (1u << k)) acc[k] += wt;
            }
            uint32_t bits = 0;
#pragma unroll
            for (int k = 0; k < 32; k++) {
                u = AI * u + acc[k];
                v = AV * v + u;
                if (v >= TH) { bits |= 1u << k; v = 0.f; }
            }
            ow[j] = bits;
        }
        int sdi = ((r * 40 + w) * 8 + o) * 4;
        sd[sdi + 0] = ow[0] << 1;
        sd[sdi + 1] = (ow[1] << 1) | (ow[0] >> 31);
        sd[sdi + 2] = (ow[2] << 1) | (ow[1] >> 31);
        sd[sdi + 3] = (ow[3] << 1) | (ow[2] >> 31);
    }
    __syncthreads();

    if (tid < 160) {   // pool phase
        int pw_ = tid % 20, c = tid / 20;
        float scale = pws[0];
        const uint32_t* p00 = &sd[((0 * 40 + 2 * pw_) * 8 + c) * 4];
        const uint32_t* p01 = &sd[((0 * 40 + 2 * pw_ + 1) * 8 + c) * 4];
        const uint32_t* p10 = &sd[((1 * 40 + 2 * pw_) * 8 + c) * 4];
        const uint32_t* p11 = &sd[((1 * 40 + 2 * pw_ + 1) * 8 + c) * 4];

        float u = 0.f, v = 0.f;
        uint32_t ow[4];
#pragma unroll
        for (int j = 0; j < 4; j++) {
            uint32_t a = p00[j], bb = p01[j], cc = p10[j], d = p11[j];
            uint32_t bits = 0;
#pragma unroll
            for (int k = 0; k < 32; k++) {
                int cnt = (int)((a >> k) & 1u) + (int)((bb >> k) & 1u)
                        + (int)((cc >> k) & 1u) + (int)((d >> k) & 1u);
                float x = (float)cnt * scale;
                u = AI * u + x;
                v = AV * v + u;
                if (v >= TH) { bits |= 1u << k; v = 0.f; }
            }
            ow[j] = bits;
        }
        sp[(c * 20 + pw_) * 4 + 0] = ow[0] << 1;
        sp[(c * 20 + pw_) * 4 + 1] = (ow[1] << 1) | (ow[0] >> 31);
        sp[(c * 20 + pw_) * 4 + 2] = (ow[2] << 1) | (ow[1] >> 31);
        sp[(c * 20 + pw_) * 4 + 3] = (ow[3] << 1) | (ow[2] >> 31);
    }
    __syncthreads();

    if (tid < 80) {    // transpose phase -> g_cp1
        int pw_ = tid >> 2, j = tid & 3;
        uint32_t wc[8];
#pragma unroll
        for (int c = 0; c < 8; c++)
            wc[c] = sp[(c * 20 + pw_) * 4 + j];
        uint8_t* dst = g_cp1 + ((size_t)n * 484 + (ph + 1) * 22 + (pw_ + 1)) * 128 + j * 32;
#pragma unroll
        for (int k = 0; k < 32; k += 4) {
            uint32_t v = 0;
#pragma unroll
            for (int q = 0; q < 4; q++) {
                uint32_t byte = 0;
#pragma unroll
                for (int c = 0; c < 8; c++)
                    byte |= ((wc[c] >> (k + q)) & 1u) << c;
                v |= byte << (q * 8);
            }
            *(uint32_t*)(dst + k) = v;
        }
    }
}

// ---------------------------------------------------------------------------
// K3: sparse conv2 o-quad (R5, proven) -> g_s3
// ---------------------------------------------------------------------------
__global__ void __launch_bounds__(128) k_conv2s(const float* __restrict__ wsrc) {
    __shared__ float4   shW4[72 * 4];
    __shared__ uint32_t shTW[128 * 3];
    __shared__ float    pre[16 * 129];
    int px = blockIdx.x, n = blockIdx.y;
    int h = px / 20, w = px % 20;
    int tid = threadIdx.x;

    for (int i = tid; i < 72 * 4; i += 128) {
        int q = i & 3, tap = i >> 2;
        int c = tap & 7, dydx = tap >> 3;
        float4 v;
        v.x = wsrc[((4 * q + 0) * 8 + c) * 9 + dydx] * 100.0f;
        v.y = wsrc[((4 * q + 1) * 8 + c) * 9 + dydx] * 100.0f;
        v.z = wsrc[((4 * q + 2) * 8 + c) * 9 + dydx] * 100.0f;
        v.w = wsrc[((4 * q + 3) * 8 + c) * 9 + dydx] * 100.0f;
        shW4[i] = v;
    }
    {
        const uint8_t* base = g_cp1 + ((size_t)n * 484 + h * 22 + w) * 128 + tid;
        uint32_t b[9];
#pragma unroll
        for (int dy = 0; dy < 3; dy++)
#pragma unroll
            for (int dx = 0; dx < 3; dx++)
                b[dy * 3 + dx] = base[(dy * 22 + dx) * 128];
        shTW[tid * 3 + 0] = b[0] | (b[1] << 8) | (b[2] << 16) | (b[3] << 24);
        shTW[tid * 3 + 1] = b[4] | (b[5] << 8) | (b[6] << 16) | (b[7] << 24);
        shTW[tid * 3 + 2] = b[8];
    }
    __syncthreads();

    int q = tid & 3, tq = tid >> 2;
#pragma unroll
    for (int i = 0; i < 4; i++) {
        int t = tq * 4 + i;
        uint32_t s0 = shTW[t * 3], s1 = shTW[t * 3 + 1], s2 = shTW[t * 3 + 2];
        unsigned long long a0 = 0ull, a1 = 0ull;
        while (s0) {
            int k = __ffs(s0) - 1; s0 &= s0 - 1;
            const ulonglong2 wv = *(const ulonglong2*)&shW4[k * 4 + q];
            add2(a0, wv.x); add2(a1, wv.y);
        }
        while (s1) {
            int k = __ffs(s1) - 1; s1 &= s1 - 1;
            const ulonglong2 wv = *(const ulonglong2*)&shW4[(32 + k) * 4 + q];
            add2(a0, wv.x); add2(a1, wv.y);
        }
        while (s2) {
            int k = __ffs(s2) - 1; s2 &= s2 - 1;
            const ulonglong2 wv = *(const ulonglong2*)&shW4[(64 + k) * 4 + q];
            add2(a0, wv.x); add2(a1, wv.y);
        }
        float2 f0 = u64f2(a0), f1 = u64f2(a1);
        pre[(4 * q + 0) * 129 + t] = f0.x;
        pre[(4 * q + 1) * 129 + t] = f0.y;
        pre[(4 * q + 2) * 129 + t] = f1.x;
        pre[(4 * q + 3) * 129 + t] = f1.y;
    }
    __syncthreads();

    if (tid < 16) {
        float u = 0.f, v = 0.f;
        uint32_t ow[4];
#pragma unroll
        for (int j = 0; j < 4; j++) {
            uint32_t bits = 0;
#pragma unroll
            for (int k = 0; k < 32; k++) {
                u = AI * u + pre[tid * 129 + j * 32 + k];
                v = AV * v + u;
                if (v >= TH) { bits |= 1u << k; v = 0.f; }
            }
            ow[j] = bits;
        }
        uint32_t d0 = ow[0] << 1;
        uint32_t d1 = (ow[1] << 1) | (ow[0] >> 31);
        uint32_t d2 = (ow[2] << 1) | (ow[1] >> 31);
        uint32_t d3 = (ow[3] << 1) | (ow[2] >> 31);
        *((uint4*)&g_s3[((size_t)((n * 16 + tid) * 400 + px)) * 4]) =
            make_uint4(d0, d1, d2, d3);
    }
}

// ---------------------------------------------------------------------------
// K_p2t: FUSED pool2 + LIF + delay + c-major u16 transpose -> g_cp2 (R14)
// ---------------------------------------------------------------------------
__global__ void __launch_bounds__(160) k_p2t(const float* __restrict__ pws) {
    __shared__ uint32_t sp[16 * 10 * 4];
    int b = blockIdx.x;
    int n = b / 10, ph = b % 10;
    int tid = threadIdx.x;

    {
        int pw_ = tid % 10, c = tid / 10;
        float scale = pws[0];
        const uint32_t* b00 = &g_s3[((size_t)((n * 16 + c) * 400 + (2 * ph) * 20 + 2 * pw_)) * 4];
        const uint32_t* b10 = b00 + 20 * 4;

        float u = 0.f, v = 0.f;
        uint32_t ow[4];
#pragma unroll
        for (int j = 0; j < 4; j++) {
            uint32_t a = b00[j], bb = b00[4 + j], cc = b10[j], d = b10[4 + j];
            uint32_t bits = 0;
#pragma unroll
            for (int k = 0; k < 32; k++) {
                int cnt = (int)((a >> k) & 1u) + (int)((bb >> k) & 1u)
                        + (int)((cc >> k) & 1u) + (int)((d >> k) & 1u);
                float x = (float)cnt * scale;
                u = AI * u + x;
                v = AV * v + u;
                if (v >= TH) { bits |= 1u << k; v = 0.f; }
            }
            ow[j] = bits;
        }
        sp[(c * 10 + pw_) * 4 + 0] = ow[0] << 1;
        sp[(c * 10 + pw_) * 4 + 1] = (ow[1] << 1) | (ow[0] >> 31);
        sp[(c * 10 + pw_) * 4 + 2] = (ow[2] << 1) | (ow[1] >> 31);
        sp[(c * 10 + pw_) * 4 + 3] = (ow[3] << 1) | (ow[2] >> 31);
    }
    __syncthreads();

    if (tid < 40) {
        int pw_ = tid >> 2, j = tid & 3;
        uint32_t wc[16];
#pragma unroll
        for (int c = 0; c < 16; c++)
            wc[c] = sp[(c * 10 + pw_) * 4 + j];
        uint16_t* dst = g_cp2 + ((size_t)n * 144 + (ph + 1) * 12 + (pw_ + 1)) * 128 + j * 32;
#pragma unroll
        for (int k = 0; k < 32; k += 2) {
            uint32_t v = 0;
#pragma unroll
            for (int c = 0; c < 16; c++) {
                v |= ((wc[c] >> k) & 1u) << c;
                v |= ((wc[c] >> (k + 1)) & 1u) << (16 + c);
            }
            *(uint32_t*)(dst + k) = v;
        }
    }
}

// ---------------------------------------------------------------------------
// K5: sparse conv3 o-quad + FUSED ballot transpose -> g_sb directly.
// c_new = px*32 + o: one block's 32 outputs = one g_sb word column (cw = px).
// ---------------------------------------------------------------------------
__global__ void __launch_bounds__(128) k_conv3s(const float* __restrict__ wsrc) {
    __shared__ float4   shW4[144 * 8];
    __shared__ uint32_t shTW[128 * 5];
    __shared__ float    pre[32 * 129];
    int px = blockIdx.x, n = blockIdx.y;
    int h = px / 10, w = px % 10;
    int tid = threadIdx.x;

    for (int i = tid; i < 144 * 8; i += 128) {
        int q = i & 7, tap = i >> 3;
        int c = tap & 15, dydx = tap >> 4;
        float4 v;
        v.x = wsrc[((4 * q + 0) * 16 + c) * 9 + dydx] * 100.0f;
        v.y = wsrc[((4 * q + 1) * 16 + c) * 9 + dydx] * 100.0f;
        v.z = wsrc[((4 * q + 2) * 16 + c) * 9 + dydx] * 100.0f;
        v.w = wsrc[((4 * q + 3) * 16 + c) * 9 + dydx] * 100.0f;
        shW4[i] = v;
    }
    {
        const uint16_t* base = g_cp2 + ((size_t)n * 144 + h * 12 + w) * 128 + tid;
        uint32_t b[9];
#pragma unroll
        for (int dy = 0; dy < 3; dy++)
#pragma unroll
            for (int dx = 0; dx < 3; dx++)
                b[dy * 3 + dx] = base[(dy * 12 + dx) * 128];
        shTW[tid * 5 + 0] = b[0] | (b[1] << 16);
        shTW[tid * 5 + 1] = b[2] | (b[3] << 16);
        shTW[tid * 5 + 2] = b[4] | (b[5] << 16);
        shTW[tid * 5 + 3] = b[6] | (b[7] << 16);
        shTW[tid * 5 + 4] = b[8];
    }
    __syncthreads();

    int q = tid & 7, tq = tid >> 3;
#pragma unroll
    for (int i = 0; i < 8; i++) {
        int t = tq * 8 + i;
        unsigned long long a0 = 0ull, a1 = 0ull;
#pragma unroll
        for (int m = 0; m < 5; m++) {
            uint32_t s = shTW[t * 5 + m];
            while (s) {
                int k = __ffs(s) - 1; s &= s - 1;
                const ulonglong2 wv = *(const ulonglong2*)&shW4[(m * 32 + k) * 8 + q];
                add2(a0, wv.x); add2(a1, wv.y);
            }
        }
        float2 f0 = u64f2(a0), f1 = u64f2(a1);
        pre[(4 * q + 0) * 129 + t] = f0.x;
        pre[(4 * q + 1) * 129 + t] = f0.y;
        pre[(4 * q + 2) * 129 + t] = f1.x;
        pre[(4 * q + 3) * 129 + t] = f1.y;
    }
    __syncthreads();

    if (tid < 32) {
        int lane = tid;   // = o
        float u = 0.f, v = 0.f;
        uint32_t prevmsb = 0;
#pragma unroll
        for (int j = 0; j < 4; j++) {
            uint32_t bits = 0;
#pragma unroll
            for (int k = 0; k < 32; k++) {
                u = AI * u + pre[lane * 129 + j * 32 + k];
                v = AV * v + u;
                if (v >= TH) { bits |= 1u << k; v = 0.f; }
            }
            uint32_t d = (bits << 1) | prevmsb;   // delayed word for t = j*32..
            prevmsb = bits >> 31;
            // ballot transpose: word for t = j*32+b has bit 'o' from lane o
            uint32_t outw = 0;
#pragma unroll
            for (int b = 0; b < 32; b++) {
                uint32_t bl = __ballot_sync(0xffffffffu, (d >> b) & 1u);
                if (lane == b) outw = bl;
            }
            g_sb[((size_t)n * 128 + j * 32 + lane) * 100 + px] = outw;
        }
    }
}

// ---------------------------------------------------------------------------
// K_fcw: WMMA bf16 FC (R13). grid (4 ot, 16 n, 2 cs), block 256.
// ---------------------------------------------------------------------------
__global__ void __launch_bounds__(256) k_fcw(float* __restrict__ dp) {
    constexpr int SPLT = 128 * 136;
    extern __shared__ __align__(16) __nv_bfloat16 sm[];
    __nv_bfloat16* sA = sm;              // 3 x [128][136]
    __nv_bfloat16* sB = sm + 3 * SPLT;   // [128][136]

    int ot = blockIdx.x, n = blockIdx.y, cs = blockIdx.z;
    int tid = threadIdx.x;
    int warp = tid >> 5;
    int wy = warp >> 2, wx = warp & 3;

    int cbeg = cs ? 13 : 0;
    int cend = cs ? 25 : 13;

    wmma::fragment<wmma::accumulator, 16, 16, 16, float> acc[4][2];
#pragma unroll
    for (int i = 0; i < 4; i++)
#pragma unroll
        for (int j = 0; j < 2; j++)
            wmma::fill_fragment(acc[i][j], 0.0f);

    for (int cc = cbeg; cc < cend; cc++) {
        __syncthreads();
        {
            int t = tid >> 1, half = tid & 1;
            const uint32_t* src = g_sb + ((size_t)n * 128 + t) * 100 + cc * 4 + half * 2;
            uint32_t w0 = src[0], w1 = src[1];
            uint32_t* d32 = (uint32_t*)(sB + t * 136 + half * 64);
#pragma unroll
            for (int b = 0; b < 16; b++)
                d32[b] = (((w0 >> (2 * b)) & 1u) ? 0x3F80u : 0u)
                       | (((w0 >> (2 * b + 1)) & 1u) ? 0x3F800000u : 0u);
#pragma unroll
            for (int b = 0; b < 16; b++)
                d32[16 + b] = (((w1 >> (2 * b)) & 1u) ? 0x3F80u : 0u)
                            | (((w1 >> (2 * b + 1)) & 1u) ? 0x3F800000u : 0u);
        }
#pragma unroll
        for (int s = 0; s < 3; s++) {
            const uint4* src = (const uint4*)
                (g_wh + ((size_t)s * 512 + ot * 128) * 3200 + cc * 128);
#pragma unroll
            for (int r8 = 0; r8 < 8; r8++) {
                int i = tid + r8 * 256;
                int r = i >> 4, q2 = i & 15;
                uint4 v = src[(size_t)r * 400 + q2];
                *(uint4*)&sA[s * SPLT + r * 136 + q2 * 8] = v;
            }
        }
        __syncthreads();

        for (int s = 0; s < 3; s++) {
#pragma unroll
            for (int k8 = 0; k8 < 8; k8++) {
                wmma::fragment<wmma::matrix_a, 16, 16, 16, __nv_bfloat16,
                               wmma::row_major> af[4];
                wmma::fragment<wmma::matrix_b, 16, 16, 16, __nv_bfloat16,
                               wmma::col_major> bf[2];
#pragma unroll
                for (int i = 0; i < 4; i++)
                    wmma::load_matrix_sync(af[i],
                        sA + s * SPLT + (wy * 64 + i * 16) * 136 + k8 * 16, 136);
#pragma unroll
                for (int j = 0; j < 2; j++)
                    wmma::load_matrix_sync(bf[j],
                        sB + (wx * 32 + j * 16) * 136 + k8 * 16, 136);
#pragma unroll
                for (int i = 0; i < 4; i++)
#pragma unroll
                    for (int j = 0; j < 2; j++)
                        wmma::mma_sync(acc[i][j], af[i], bf[j], acc[i][j]);
            }
        }
    }

    float* base = dp + ((size_t)(cs * 16 + n) * 512 + ot * 128) * 128;
#pragma unroll
    for (int i = 0; i < 4; i++)
#pragma unroll
        for (int j = 0; j < 2; j++)
            wmma::store_matrix_sync(
                base + (wy * 64 + i * 16) * 128 + wx * 32 + j * 16,
                acc[i][j], 128, wmma::mem_row_major);
}

// ---------------------------------------------------------------------------
// K_lif2: sum 2 partials + LIF + output delay-shift -> d_out
// ---------------------------------------------------------------------------
__global__ void k_lif2(float* __restrict__ out) {
    const size_t S = (size_t)16 * 512 * 128;
    int idx = blockIdx.x * blockDim.x + threadIdx.x;
    const float* a = &g_dp2[(size_t)idx * 128];
    float* op = &out[(size_t)idx * 128];
    float u = 0.f, v = 0.f, prev = 0.f;
#pragma unroll 8
    for (int t = 0; t < 128; t++) {
        op[t] = prev;
        float x = a[t] + a[t + S];
        u = AI * u + x;
        v = AV * v + u;
        if (v >= TH) { prev = 1.f; v = 0.f; } else { prev = 0.f; }
    }
}

// ---------------------------------------------------------------------------
extern "C" void kernel_launch(void* const* d_in, const int* in_sizes, int n_in,
                              void* d_out, int out_size) {
    const float* spike = (const float*)d_in[0];
    const float* c1w   = (const float*)d_in[1];
    const float* c2w   = (const float*)d_in[2];
    const float* c3w   = (const float*)d_in[3];
    const float* p1w   = (const float*)d_in[4];
    const float* p2w   = (const float*)d_in[5];
    const float* fcw   = (const float*)d_in[6];
    float* out = (float*)d_out;

    float* dp;
    cudaGetSymbolAddress((void**)&dp, g_dp2);

    const int FCW_SMEM = 4 * 128 * 136 * 2;   // 139264 B
    cudaFuncSetAttribute((const void*)k_fcw,
                         cudaFuncAttributeMaxDynamicSharedMemorySize, FCW_SMEM);

    // one-time side stream + fork/join events (created outside capture on the
    // first (correctness) call; graph capture turns the events into edges)
    static cudaStream_t s2 = nullptr;
    static cudaEvent_t evFork = nullptr, evJoin = nullptr;
    if (s2 == nullptr) {
        cudaStreamCreate(&s2);
        cudaEventCreateWithFlags(&evFork, cudaEventDisableTiming);
        cudaEventCreateWithFlags(&evJoin, cudaEventDisableTiming);
    }

    // fork: W split runs concurrently with the spike pipeline
    cudaEventRecord(evFork, 0);
    cudaStreamWaitEvent(s2, evFork, 0);
    k_wsplit<<<3200, 256, 0, s2>>>(fcw);
    cudaEventRecord(evJoin, s2);

    k_pack<<<200, 256>>>(spike);
    k_c1p<<<320, 640>>>(c1w, p1w);                     // conv1+pool1+tr -> g_cp1
    k_conv2s<<<dim3(400, 16), 128>>>(c2w);             // -> g_s3
    k_p2t<<<160, 160>>>(p2w);                          // pool2+tr -> g_cp2
    k_conv3s<<<dim3(100, 16), 128>>>(c3w);             // -> g_sb directly

    cudaStreamWaitEvent(0, evJoin, 0);                 // join before FC
    k_fcw<<<dim3(4, 16, 2), 256, FCW_SMEM>>>(dp);      // WMMA bf16 FC
    k_lif2<<<32, 256>>>(out);
}

// round 16
// speedup vs baseline: 1.0060x; 1.0060x over previous
#include <cuda_runtime.h>
#include <cuda_bf16.h>
#include <mma.h>
#include <stdint.h>

using namespace nvcuda;

// Loihi CUBA constants
#define AI 0.75f
#define AV 0.96875f
#define TH 100.0f

__device__ __forceinline__ void add2(unsigned long long& a, unsigned long long b) {
    asm("add.rn.f32x2 %0, %0, %1;" : "+l"(a) : "l"(b));
}
__device__ __forceinline__ float2 u64f2(unsigned long long v) {
    float2 f; asm("mov.b64 {%0, %1}, %2;" : "=f"(f.x), "=f"(f.y) : "l"(v)); return f;
}

// ---------------------------------------------------------------------------
// Buffers (bit k of word j = spike at t = j*32+k; all streams pre-delayed)
// ---------------------------------------------------------------------------
__device__ uint32_t g_s0[16 * 2  * 40 * 40 * 4];
__device__ uint32_t g_s3[16 * 16 * 20 * 20 * 4];
__device__ uint32_t g_s5[16 * 3200 * 4];
__device__ uint32_t g_sb[16 * 128 * 100];           // c-major words per (n,t)
__device__ uint8_t  g_cp1[16 * 22 * 22 * 128];      // pool1 out, c-major bytes (padded)
__device__ uint16_t g_cp2[16 * 12 * 12 * 128];      // pool2 out, c-major u16 (padded)
__device__ __nv_bfloat16 g_wh[3 * 512 * 3200];      // FC W bf16 splits
__device__ float    g_dp2[2 * 16 * 512 * 128];      // fc partials (2 c-halves)

// ---------------------------------------------------------------------------
// K0: pack raw float spikes -> bit words
// ---------------------------------------------------------------------------
__global__ void k_pack(const float* __restrict__ sp) {
    int idx = blockIdx.x * blockDim.x + threadIdx.x;
    const float4* p = (const float4*)(sp + (size_t)idx * 128);
    uint32_t w[4];
#pragma unroll
    for (int j = 0; j < 4; j++) {
        uint32_t b = 0;
#pragma unroll
        for (int q = 0; q < 8; q++) {
            float4 v = p[j * 8 + q];
            b |= (v.x > 0.5f ? 1u : 0u) << (q * 4 + 0);
            b |= (v.y > 0.5f ? 1u : 0u) << (q * 4 + 1);
            b |= (v.z > 0.5f ? 1u : 0u) << (q * 4 + 2);
            b |= (v.w > 0.5f ? 1u : 0u) << (q * 4 + 3);
        }
        w[j] = b;
    }
    *((uint4*)&g_s0[(size_t)idx * 4]) = make_uint4(w[0], w[1], w[2], w[3]);
}

// ---------------------------------------------------------------------------
// K_wsplit: FC W fp32 -> 3 bf16 splits (hi, mid, lo). Coalesced (R14 layout).
// ---------------------------------------------------------------------------
__global__ void k_wsplit(const float* __restrict__ W) {
    int i = blockIdx.x * blockDim.x + threadIdx.x;
    float a = W[2 * i], b = W[2 * i + 1];
    __nv_bfloat16 ha = __float2bfloat16(a), hb = __float2bfloat16(b);
    float ra = a - __bfloat162float(ha), rb = b - __bfloat162float(hb);
    __nv_bfloat16 ma = __float2bfloat16(ra), mb = __float2bfloat16(rb);
    float sa = ra - __bfloat162float(ma), sb = rb - __bfloat162float(mb);
    __nv_bfloat16 la = __float2bfloat16(sa), lb = __float2bfloat16(sb);
    uint32_t* g = (uint32_t*)g_wh;
    uint16_t uha = *(uint16_t*)&ha, uhb = *(uint16_t*)&hb;
    uint16_t uma = *(uint16_t*)&ma, umb = *(uint16_t*)&mb;
    uint16_t ula = *(uint16_t*)&la, ulb = *(uint16_t*)&lb;
    g[i]              = (uint32_t)uha | ((uint32_t)uhb << 16);
    g[819200 + i]     = (uint32_t)uma | ((uint32_t)umb << 16);
    g[2 * 819200 + i] = (uint32_t)ula | ((uint32_t)ulb << 16);
}

// ---------------------------------------------------------------------------
// K_c1p: FUSED conv1 + LIF + delay + 2x2 pool + LIF + delay + c-major
// transpose -> g_cp1. Block = (n, ph), 640 thr. (R14, proven)
// ---------------------------------------------------------------------------
__global__ void __launch_bounds__(640) k_c1p(const float* __restrict__ cw,
                                             const float* __restrict__ pws) {
    __shared__ uint32_t sh[2 * 4 * 42 * 4];
    __shared__ uint32_t sd[2 * 40 * 8 * 4];
    __shared__ uint32_t sp[8 * 20 * 4];
    int b = blockIdx.x;
    int n = b / 20, ph = b % 20;
    int tid = threadIdx.x;

    for (int i = tid; i < 2 * 4 * 42 * 4; i += 640) {
        int j = i & 3;
        int t2 = i >> 2;
        int wx = t2 % 42;
        int t3 = t2 / 42;
        int row = t3 % 4;
        int c = t3 / 4;
        int hh = 2 * ph - 1 + row, ws = wx - 1;
        uint32_t v = 0;
        if (hh >= 0 && hh < 40 && ws >= 0 && ws < 40)
            v = g_s0[(((n * 2 + c) * 40 + hh) * 40 + ws) * 4 + j];
        sh[((c * 4 + row) * 42 + wx) * 4 + j] = v;
    }
    __syncthreads();

    {   // conv phase: thread = (r, w, o)
        int r = tid / 320;
        int rt = tid % 320;
        int w = rt % 40, o = rt / 40;
        float wg[18];
#pragma unroll
        for (int i = 0; i < 18; i++) wg[i] = cw[o * 18 + i] * 20.0f;

        float u = 0.f, v = 0.f;
        uint32_t ow[4];
#pragma unroll
        for (int j = 0; j < 4; j++) {
            float acc[32];
#pragma unroll
            for (int k = 0; k < 32; k++) acc[k] = 0.f;
#pragma unroll
            for (int c = 0; c < 2; c++)
#pragma unroll
            for (int dy = 0; dy < 3; dy++)
#pragma unroll
            for (int dx = 0; dx < 3; dx++) {
                uint32_t wd = sh[((c * 4 + (r + dy)) * 42 + (w + dx)) * 4 + j];
                float wt = wg[c * 9 + dy * 3 + dx];
#pragma unroll
                for (int k = 0; k < 32; k++)
                    if (wd & (1u << k)) acc[k] += wt;
            }
            uint32_t bits = 0;
#pragma unroll
            for (int k = 0; k < 32; k++) {
                u = AI * u + acc[k];
                v = AV * v + u;
                if (v >= TH) { bits |= 1u << k; v = 0.f; }
            }
            ow[j] = bits;
        }
        int sdi = ((r * 40 + w) * 8 + o) * 4;
        sd[sdi + 0] = ow[0] << 1;
        sd[sdi + 1] = (ow[1] << 1) | (ow[0] >> 31);
        sd[sdi + 2] = (ow[2] << 1) | (ow[1] >> 31);
        sd[sdi + 3] = (ow[3] << 1) | (ow[2] >> 31);
    }
    __syncthreads();

    if (tid < 160) {   // pool phase
        int pw_ = tid % 20, c = tid / 20;
        float scale = pws[0];
        const uint32_t* p00 = &sd[((0 * 40 + 2 * pw_) * 8 + c) * 4];
        const uint32_t* p01 = &sd[((0 * 40 + 2 * pw_ + 1) * 8 + c) * 4];
        const uint32_t* p10 = &sd[((1 * 40 + 2 * pw_) * 8 + c) * 4];
        const uint32_t* p11 = &sd[((1 * 40 + 2 * pw_ + 1) * 8 + c) * 4];

        float u = 0.f, v = 0.f;
        uint32_t ow[4];
#pragma unroll
        for (int j = 0; j < 4; j++) {
            uint32_t a = p00[j], bb = p01[j], cc = p10[j], d = p11[j];
            uint32_t bits = 0;
#pragma unroll
            for (int k = 0; k < 32; k++) {
                int cnt = (int)((a >> k) & 1u) + (int)((bb >> k) & 1u)
                        + (int)((cc >> k) & 1u) + (int)((d >> k) & 1u);
                float x = (float)cnt * scale;
                u = AI * u + x;
                v = AV * v + u;
                if (v >= TH) { bits |= 1u << k; v = 0.f; }
            }
            ow[j] = bits;
        }
        sp[(c * 20 + pw_) * 4 + 0] = ow[0] << 1;
        sp[(c * 20 + pw_) * 4 + 1] = (ow[1] << 1) | (ow[0] >> 31);
        sp[(c * 20 + pw_) * 4 + 2] = (ow[2] << 1) | (ow[1] >> 31);
        sp[(c * 20 + pw_) * 4 + 3] = (ow[3] << 1) | (ow[2] >> 31);
    }
    __syncthreads();

    if (tid < 80) {    // transpose phase -> g_cp1
        int pw_ = tid >> 2, j = tid & 3;
        uint32_t wc[8];
#pragma unroll
        for (int c = 0; c < 8; c++)
            wc[c] = sp[(c * 20 + pw_) * 4 + j];
        uint8_t* dst = g_cp1 + ((size_t)n * 484 + (ph + 1) * 22 + (pw_ + 1)) * 128 + j * 32;
#pragma unroll
        for (int k = 0; k < 32; k += 4) {
            uint32_t v = 0;
#pragma unroll
            for (int q = 0; q < 4; q++) {
                uint32_t byte = 0;
#pragma unroll
                for (int c = 0; c < 8; c++)
                    byte |= ((wc[c] >> (k + q)) & 1u) << c;
                v |= byte << (q * 8);
            }
            *(uint32_t*)(dst + k) = v;
        }
    }
}

// ---------------------------------------------------------------------------
// K3: sparse conv2 o-quad (R5, proven) -> g_s3
// ---------------------------------------------------------------------------
__global__ void __launch_bounds__(128) k_conv2s(const float* __restrict__ wsrc) {
    __shared__ float4   shW4[72 * 4];
    __shared__ uint32_t shTW[128 * 3];
    __shared__ float    pre[16 * 129];
    int px = blockIdx.x, n = blockIdx.y;
    int h = px / 20, w = px % 20;
    int tid = threadIdx.x;

    for (int i = tid; i < 72 * 4; i += 128) {
        int q = i & 3, tap = i >> 2;
        int c = tap & 7, dydx = tap >> 3;
        float4 v;
        v.x = wsrc[((4 * q + 0) * 8 + c) * 9 + dydx] * 100.0f;
        v.y = wsrc[((4 * q + 1) * 8 + c) * 9 + dydx] * 100.0f;
        v.z = wsrc[((4 * q + 2) * 8 + c) * 9 + dydx] * 100.0f;
        v.w = wsrc[((4 * q + 3) * 8 + c) * 9 + dydx] * 100.0f;
        shW4[i] = v;
    }
    {
        const uint8_t* base = g_cp1 + ((size_t)n * 484 + h * 22 + w) * 128 + tid;
        uint32_t b[9];
#pragma unroll
        for (int dy = 0; dy < 3; dy++)
#pragma unroll
            for (int dx = 0; dx < 3; dx++)
                b[dy * 3 + dx] = base[(dy * 22 + dx) * 128];
        shTW[tid * 3 + 0] = b[0] | (b[1] << 8) | (b[2] << 16) | (b[3] << 24);
        shTW[tid * 3 + 1] = b[4] | (b[5] << 8) | (b[6] << 16) | (b[7] << 24);
        shTW[tid * 3 + 2] = b[8];
    }
    __syncthreads();

    int q = tid & 3, tq = tid >> 2;
#pragma unroll
    for (int i = 0; i < 4; i++) {
        int t = tq * 4 + i;
        uint32_t s0 = shTW[t * 3], s1 = shTW[t * 3 + 1], s2 = shTW[t * 3 + 2];
        unsigned long long a0 = 0ull, a1 = 0ull;
        while (s0) {
            int k = __ffs(s0) - 1; s0 &= s0 - 1;
            const ulonglong2 wv = *(const ulonglong2*)&shW4[k * 4 + q];
            add2(a0, wv.x); add2(a1, wv.y);
        }
        while (s1) {
            int k = __ffs(s1) - 1; s1 &= s1 - 1;
            const ulonglong2 wv = *(const ulonglong2*)&shW4[(32 + k) * 4 + q];
            add2(a0, wv.x); add2(a1, wv.y);
        }
        while (s2) {
            int k = __ffs(s2) - 1; s2 &= s2 - 1;
            const ulonglong2 wv = *(const ulonglong2*)&shW4[(64 + k) * 4 + q];
            add2(a0, wv.x); add2(a1, wv.y);
        }
        float2 f0 = u64f2(a0), f1 = u64f2(a1);
        pre[(4 * q + 0) * 129 + t] = f0.x;
        pre[(4 * q + 1) * 129 + t] = f0.y;
        pre[(4 * q + 2) * 129 + t] = f1.x;
        pre[(4 * q + 3) * 129 + t] = f1.y;
    }
    __syncthreads();

    if (tid < 16) {
        float u = 0.f, v = 0.f;
        uint32_t ow[4];
#pragma unroll
        for (int j = 0; j < 4; j++) {
            uint32_t bits = 0;
#pragma unroll
            for (int k = 0; k < 32; k++) {
                u = AI * u + pre[tid * 129 + j * 32 + k];
                v = AV * v + u;
                if (v >= TH) { bits |= 1u << k; v = 0.f; }
            }
            ow[j] = bits;
        }
        uint32_t d0 = ow[0] << 1;
        uint32_t d1 = (ow[1] << 1) | (ow[0] >> 31);
        uint32_t d2 = (ow[2] << 1) | (ow[1] >> 31);
        uint32_t d3 = (ow[3] << 1) | (ow[2] >> 31);
        *((uint4*)&g_s3[((size_t)((n * 16 + tid) * 400 + px)) * 4]) =
            make_uint4(d0, d1, d2, d3);
    }
}

// ---------------------------------------------------------------------------
// K_p2t: FUSED pool2 + LIF + delay + c-major u16 transpose -> g_cp2 (R14)
// ---------------------------------------------------------------------------
__global__ void __launch_bounds__(160) k_p2t(const float* __restrict__ pws) {
    __shared__ uint32_t sp[16 * 10 * 4];
    int b = blockIdx.x;
    int n = b / 10, ph = b % 10;
    int tid = threadIdx.x;

    {
        int pw_ = tid % 10, c = tid / 10;
        float scale = pws[0];
        const uint32_t* b00 = &g_s3[((size_t)((n * 16 + c) * 400 + (2 * ph) * 20 + 2 * pw_)) * 4];
        const uint32_t* b10 = b00 + 20 * 4;

        float u = 0.f, v = 0.f;
        uint32_t ow[4];
#pragma unroll
        for (int j = 0; j < 4; j++) {
            uint32_t a = b00[j], bb = b00[4 + j], cc = b10[j], d = b10[4 + j];
            uint32_t bits = 0;
#pragma unroll
            for (int k = 0; k < 32; k++) {
                int cnt = (int)((a >> k) & 1u) + (int)((bb >> k) & 1u)
                        + (int)((cc >> k) & 1u) + (int)((d >> k) & 1u);
                float x = (float)cnt * scale;
                u = AI * u + x;
                v = AV * v + u;
                if (v >= TH) { bits |= 1u << k; v = 0.f; }
            }
            ow[j] = bits;
        }
        sp[(c * 10 + pw_) * 4 + 0] = ow[0] << 1;
        sp[(c * 10 + pw_) * 4 + 1] = (ow[1] << 1) | (ow[0] >> 31);
        sp[(c * 10 + pw_) * 4 + 2] = (ow[2] << 1) | (ow[1] >> 31);
        sp[(c * 10 + pw_) * 4 + 3] = (ow[3] << 1) | (ow[2] >> 31);
    }
    __syncthreads();

    if (tid < 40) {
        int pw_ = tid >> 2, j = tid & 3;
        uint32_t wc[16];
#pragma unroll
        for (int c = 0; c < 16; c++)
            wc[c] = sp[(c * 10 + pw_) * 4 + j];
        uint16_t* dst = g_cp2 + ((size_t)n * 144 + (ph + 1) * 12 + (pw_ + 1)) * 128 + j * 32;
#pragma unroll
        for (int k = 0; k < 32; k += 2) {
            uint32_t v = 0;
#pragma unroll
            for (int c = 0; c < 16; c++) {
                v |= ((wc[c] >> k) & 1u) << c;
                v |= ((wc[c] >> (k + 1)) & 1u) << (16 + c);
            }
            *(uint32_t*)(dst + k) = v;
        }
    }
}

// ---------------------------------------------------------------------------
// K5: sparse conv3 o-quad (R5, proven) -> g_s5
// ---------------------------------------------------------------------------
__global__ void __launch_bounds__(128) k_conv3s(const float* __restrict__ wsrc) {
    __shared__ float4   shW4[144 * 8];
    __shared__ uint32_t shTW[128 * 5];
    __shared__ float    pre[32 * 129];
    int px = blockIdx.x, n = blockIdx.y;
    int h = px / 10, w = px % 10;
    int tid = threadIdx.x;

    for (int i = tid; i < 144 * 8; i += 128) {
        int q = i & 7, tap = i >> 3;
        int c = tap & 15, dydx = tap >> 4;
        float4 v;
        v.x = wsrc[((4 * q + 0) * 16 + c) * 9 + dydx] * 100.0f;
        v.y = wsrc[((4 * q + 1) * 16 + c) * 9 + dydx] * 100.0f;
        v.z = wsrc[((4 * q + 2) * 16 + c) * 9 + dydx] * 100.0f;
        v.w = wsrc[((4 * q + 3) * 16 + c) * 9 + dydx] * 100.0f;
        shW4[i] = v;
    }
    {
        const uint16_t* base = g_cp2 + ((size_t)n * 144 + h * 12 + w) * 128 + tid;
        uint32_t b[9];
#pragma unroll
        for (int dy = 0; dy < 3; dy++)
#pragma unroll
            for (int dx = 0; dx < 3; dx++)
                b[dy * 3 + dx] = base[(dy * 12 + dx) * 128];
        shTW[tid * 5 + 0] = b[0] | (b[1] << 16);
        shTW[tid * 5 + 1] = b[2] | (b[3] << 16);
        shTW[tid * 5 + 2] = b[4] | (b[5] << 16);
        shTW[tid * 5 + 3] = b[6] | (b[7] << 16);
        shTW[tid * 5 + 4] = b[8];
    }
    __syncthreads();

    int q = tid & 7, tq = tid >> 3;
#pragma unroll
    for (int i = 0; i < 8; i++) {
        int t = tq * 8 + i;
        unsigned long long a0 = 0ull, a1 = 0ull;
#pragma unroll
        for (int m = 0; m < 5; m++) {
            uint32_t s = shTW[t * 5 + m];
            while (s) {
                int k = __ffs(s) - 1; s &= s - 1;
                const ulonglong2 wv = *(const ulonglong2*)&shW4[(m * 32 + k) * 8 + q];
                add2(a0, wv.x); add2(a1, wv.y);
            }
        }
        float2 f0 = u64f2(a0), f1 = u64f2(a1);
        pre[(4 * q + 0) * 129 + t] = f0.x;
        pre[(4 * q + 1) * 129 + t] = f0.y;
        pre[(4 * q + 2) * 129 + t] = f1.x;
        pre[(4 * q + 3) * 129 + t] = f1.y;
    }
    __syncthreads();

    if (tid < 32) {
        float u = 0.f, v = 0.f;
        uint32_t ow[4];
#pragma unroll
        for (int j = 0; j < 4; j++) {
            uint32_t bits = 0;
#pragma unroll
            for (int k = 0; k < 32; k++) {
                u = AI * u + pre[tid * 129 + j * 32 + k];
                v = AV * v + u;
                if (v >= TH) { bits |= 1u << k; v = 0.f; }
            }
            ow[j] = bits;
        }
        uint32_t d0 = ow[0] << 1;
        uint32_t d1 = (ow[1] << 1) | (ow[0] >> 31);
        uint32_t d2 = (ow[2] << 1) | (ow[1] >> 31);
        uint32_t d3 = (ow[3] << 1) | (ow[2] >> 31);
        *((uint4*)&g_s5[((size_t)(n * 3200 + tid * 100 + px)) * 4]) =
            make_uint4(d0, d1, d2, d3);
    }
}

// ---------------------------------------------------------------------------
// K5b: bit transpose t-major -> c-major (FC input)
// ---------------------------------------------------------------------------
__global__ void k_trans() {
    int gw = (blockIdx.x * blockDim.x + threadIdx.x) >> 5;
    int lane = threadIdx.x & 31;
    int n = gw / 400;
    int r = gw % 400;
    int cw = r >> 2;
    int j = r & 3;
    uint32_t w = g_s5[((size_t)n * 3200 + cw * 32 + lane) * 4 + j];
    uint32_t out = 0;
#pragma unroll
    for (int b = 0; b < 32; b++) {
        uint32_t bl = __ballot_sync(0xffffffffu, (w >> b) & 1u);
        if (lane == b) out = bl;
    }
    g_sb[((size_t)n * 128 + j * 32 + lane) * 100 + cw] = out;
}

// ---------------------------------------------------------------------------
// K_fcw: WMMA bf16 FC (R13/R14). grid (4 ot, 16 n, 2 cs), block 256.
// ---------------------------------------------------------------------------
__global__ void __launch_bounds__(256) k_fcw(float* __restrict__ dp) {
    constexpr int SPLT = 128 * 136;
    extern __shared__ __align__(16) __nv_bfloat16 sm[];
    __nv_bfloat16* sA = sm;              // 3 x [128][136]
    __nv_bfloat16* sB = sm + 3 * SPLT;   // [128][136]

    int ot = blockIdx.x, n = blockIdx.y, cs = blockIdx.z;
    int tid = threadIdx.x;
    int warp = tid >> 5;
    int wy = warp >> 2, wx = warp & 3;

    int cbeg = cs ? 13 : 0;
    int cend = cs ? 25 : 13;

    wmma::fragment<wmma::accumulator, 16, 16, 16, float> acc[4][2];
#pragma unroll
    for (int i = 0; i < 4; i++)
#pragma unroll
        for (int j = 0; j < 2; j++)
            wmma::fill_fragment(acc[i][j], 0.0f);

    for (int cc = cbeg; cc < cend; cc++) {
        __syncthreads();
        {
            int t = tid >> 1, half = tid & 1;
            const uint32_t* src = g_sb + ((size_t)n * 128 + t) * 100 + cc * 4 + half * 2;
            uint32_t w0 = src[0], w1 = src[1];
            uint32_t* d32 = (uint32_t*)(sB + t * 136 + half * 64);
#pragma unroll
            for (int b = 0; b < 16; b++)
                d32[b] = (((w0 >> (2 * b)) & 1u) ? 0x3F80u : 0u)
                       | (((w0 >> (2 * b + 1)) & 1u) ? 0x3F800000u : 0u);
#pragma unroll
            for (int b = 0; b < 16; b++)
                d32[16 + b] = (((w1 >> (2 * b)) & 1u) ? 0x3F80u : 0u)
                            | (((w1 >> (2 * b + 1)) & 1u) ? 0x3F800000u : 0u);
        }
#pragma unroll
        for (int s = 0; s < 3; s++) {
            const uint4* src = (const uint4*)
                (g_wh + ((size_t)s * 512 + ot * 128) * 3200 + cc * 128);
#pragma unroll
            for (int r8 = 0; r8 < 8; r8++) {
                int i = tid + r8 * 256;
                int r = i >> 4, q2 = i & 15;
                uint4 v = src[(size_t)r * 400 + q2];
                *(uint4*)&sA[s * SPLT + r * 136 + q2 * 8] = v;
            }
        }
        __syncthreads();

        for (int s = 0; s < 3; s++) {
#pragma unroll
            for (int k8 = 0; k8 < 8; k8++) {
                wmma::fragment<wmma::matrix_a, 16, 16, 16, __nv_bfloat16,
                               wmma::row_major> af[4];
                wmma::fragment<wmma::matrix_b, 16, 16, 16, __nv_bfloat16,
                               wmma::col_major> bf[2];
#pragma unroll
                for (int i = 0; i < 4; i++)
                    wmma::load_matrix_sync(af[i],
                        sA + s * SPLT + (wy * 64 + i * 16) * 136 + k8 * 16, 136);
#pragma unroll
                for (int j = 0; j < 2; j++)
                    wmma::load_matrix_sync(bf[j],
                        sB + (wx * 32 + j * 16) * 136 + k8 * 16, 136);
#pragma unroll
                for (int i = 0; i < 4; i++)
#pragma unroll
                    for (int j = 0; j < 2; j++)
                        wmma::mma_sync(acc[i][j], af[i], bf[j], acc[i][j]);
            }
        }
    }

    float* base = dp + ((size_t)(cs * 16 + n) * 512 + ot * 128) * 128;
#pragma unroll
    for (int i = 0; i < 4; i++)
#pragma unroll
        for (int j = 0; j < 2; j++)
            wmma::store_matrix_sync(
                base + (wy * 64 + i * 16) * 128 + wx * 32 + j * 16,
                acc[i][j], 128, wmma::mem_row_major);
}

// ---------------------------------------------------------------------------
// K_lif2: sum 2 partials + LIF + output delay-shift -> d_out
// ---------------------------------------------------------------------------
__global__ void k_lif2(float* __restrict__ out) {
    const size_t S = (size_t)16 * 512 * 128;
    int idx = blockIdx.x * blockDim.x + threadIdx.x;
    const float* a = &g_dp2[(size_t)idx * 128];
    float* op = &out[(size_t)idx * 128];
    float u = 0.f, v = 0.f, prev = 0.f;
#pragma unroll 8
    for (int t = 0; t < 128; t++) {
        op[t] = prev;
        float x = a[t] + a[t + S];
        u = AI * u + x;
        v = AV * v + u;
        if (v >= TH) { prev = 1.f; v = 0.f; } else { prev = 0.f; }
    }
}

// ---------------------------------------------------------------------------
extern "C" void kernel_launch(void* const* d_in, const int* in_sizes, int n_in,
                              void* d_out, int out_size) {
    const float* spike = (const float*)d_in[0];
    const float* c1w   = (const float*)d_in[1];
    const float* c2w   = (const float*)d_in[2];
    const float* c3w   = (const float*)d_in[3];
    const float* p1w   = (const float*)d_in[4];
    const float* p2w   = (const float*)d_in[5];
    const float* fcw   = (const float*)d_in[6];
    float* out = (float*)d_out;

    float* dp;
    cudaGetSymbolAddress((void**)&dp, g_dp2);

    const int FCW_SMEM = 4 * 128 * 136 * 2;   // 139264 B
    cudaFuncSetAttribute((const void*)k_fcw,
                         cudaFuncAttributeMaxDynamicSharedMemorySize, FCW_SMEM);

    // one-time side stream + fork/join events (capture-legal; R15 validated
    // the mechanism, this time with the coalesced wsplit)
    static cudaStream_t s2 = nullptr;
    static cudaEvent_t evFork = nullptr, evJoin = nullptr;
    if (s2 == nullptr) {
        cudaStreamCreate(&s2);
        cudaEventCreateWithFlags(&evFork, cudaEventDisableTiming);
        cudaEventCreateWithFlags(&evJoin, cudaEventDisableTiming);
    }

    cudaEventRecord(evFork, 0);
    cudaStreamWaitEvent(s2, evFork, 0);
    k_wsplit<<<3200, 256, 0, s2>>>(fcw);               // overlapped W split
    cudaEventRecord(evJoin, s2);

    k_pack<<<200, 256>>>(spike);
    k_c1p<<<320, 640>>>(c1w, p1w);                     // conv1+pool1+tr -> g_cp1
    k_conv2s<<<dim3(400, 16), 128>>>(c2w);             // -> g_s3
    k_p2t<<<160, 160>>>(p2w);                          // pool2+tr -> g_cp2
    k_conv3s<<<dim3(100, 16), 128>>>(c3w);             // -> g_s5
    k_trans<<<800, 256>>>();                           // -> g_sb

    cudaStreamWaitEvent(0, evJoin, 0);                 // join before FC
    k_fcw<<<dim3(4, 16, 2), 256, FCW_SMEM>>>(dp);      // WMMA bf16 FC
    k_lif2<<<32, 256>>>(out);
}

// round 17
// speedup vs baseline: 1.0087x; 1.0027x over previous
#include <cuda_runtime.h>
#include <cuda_bf16.h>
#include <mma.h>
#include <stdint.h>

using namespace nvcuda;

// Loihi CUBA constants
#define AI 0.75f
#define AV 0.96875f
#define TH 100.0f

__device__ __forceinline__ void add2(unsigned long long& a, unsigned long long b) {
    asm("add.rn.f32x2 %0, %0, %1;" : "+l"(a) : "l"(b));
}
__device__ __forceinline__ float2 u64f2(unsigned long long v) {
    float2 f; asm("mov.b64 {%0, %1}, %2;" : "=f"(f.x), "=f"(f.y) : "l"(v)); return f;
}

// ---------------------------------------------------------------------------
// Buffers (bit k of word j = spike at t = j*32+k; all streams pre-delayed)
// ---------------------------------------------------------------------------
__device__ uint32_t g_s0[16 * 2  * 40 * 40 * 4];
__device__ uint32_t g_s3[16 * 16 * 20 * 20 * 4];
__device__ uint32_t g_s5[16 * 3200 * 4];
__device__ uint32_t g_sb[16 * 128 * 100];           // c-major words per (n,t)
__device__ uint8_t  g_cp1[16 * 22 * 22 * 128];      // pool1 out, c-major bytes (padded)
__device__ uint16_t g_cp2[16 * 12 * 12 * 128];      // pool2 out, c-major u16 (padded)
__device__ __nv_bfloat16 g_wh[3 * 512 * 3200];      // FC W bf16 splits
__device__ float    g_dp2[2 * 16 * 512 * 128];      // fc partials (2 c-halves)

// ---------------------------------------------------------------------------
// K_pw: MERGED input pack + FC W 3-split (independent work, one kernel).
// blocks [0, 3200): wsplit path (thread i = pair of W elements)
// blocks [3200, 3400): pack path (thread = one (n,c,h,w) neuron)
// Both paths byte-identical to round 14's k_wsplit / k_pack.
// ---------------------------------------------------------------------------
__global__ void __launch_bounds__(256) k_pw(const float* __restrict__ sp,
                                            const float* __restrict__ W) {
    if (blockIdx.x < 3200) {
        int i = blockIdx.x * 256 + threadIdx.x;
        float a = W[2 * i], b = W[2 * i + 1];
        __nv_bfloat16 ha = __float2bfloat16(a), hb = __float2bfloat16(b);
        float ra = a - __bfloat162float(ha), rb = b - __bfloat162float(hb);
        __nv_bfloat16 ma = __float2bfloat16(ra), mb = __float2bfloat16(rb);
        float sa = ra - __bfloat162float(ma), sb = rb - __bfloat162float(mb);
        __nv_bfloat16 la = __float2bfloat16(sa), lb = __float2bfloat16(sb);
        uint32_t* g = (uint32_t*)g_wh;
        uint16_t uha = *(uint16_t*)&ha, uhb = *(uint16_t*)&hb;
        uint16_t uma = *(uint16_t*)&ma, umb = *(uint16_t*)&mb;
        uint16_t ula = *(uint16_t*)&la, ulb = *(uint16_t*)&lb;
        g[i]              = (uint32_t)uha | ((uint32_t)uhb << 16);
        g[819200 + i]     = (uint32_t)uma | ((uint32_t)umb << 16);
        g[2 * 819200 + i] = (uint32_t)ula | ((uint32_t)ulb << 16);
    } else {
        int idx = (blockIdx.x - 3200) * 256 + threadIdx.x;   // 51200 neurons
        const float4* p = (const float4*)(sp + (size_t)idx * 128);
        uint32_t w[4];
#pragma unroll
        for (int j = 0; j < 4; j++) {
            uint32_t b = 0;
#pragma unroll
            for (int q = 0; q < 8; q++) {
                float4 v = p[j * 8 + q];
                b |= (v.x > 0.5f ? 1u : 0u) << (q * 4 + 0);
                b |= (v.y > 0.5f ? 1u : 0u) << (q * 4 + 1);
                b |= (v.z > 0.5f ? 1u : 0u) << (q * 4 + 2);
                b |= (v.w > 0.5f ? 1u : 0u) << (q * 4 + 3);
            }
            w[j] = b;
        }
        *((uint4*)&g_s0[(size_t)idx * 4]) = make_uint4(w[0], w[1], w[2], w[3]);
    }
}

// ---------------------------------------------------------------------------
// K_c1p: FUSED conv1 + LIF + delay + 2x2 pool + LIF + delay + c-major
// transpose -> g_cp1. Block = (n, ph), 640 thr. (R14, proven)
// ---------------------------------------------------------------------------
__global__ void __launch_bounds__(640) k_c1p(const float* __restrict__ cw,
                                             const float* __restrict__ pws) {
    __shared__ uint32_t sh[2 * 4 * 42 * 4];
    __shared__ uint32_t sd[2 * 40 * 8 * 4];
    __shared__ uint32_t sp[8 * 20 * 4];
    int b = blockIdx.x;
    int n = b / 20, ph = b % 20;
    int tid = threadIdx.x;

    for (int i = tid; i < 2 * 4 * 42 * 4; i += 640) {
        int j = i & 3;
        int t2 = i >> 2;
        int wx = t2 % 42;
        int t3 = t2 / 42;
        int row = t3 % 4;
        int c = t3 / 4;
        int hh = 2 * ph - 1 + row, ws = wx - 1;
        uint32_t v = 0;
        if (hh >= 0 && hh < 40 && ws >= 0 && ws < 40)
            v = g_s0[(((n * 2 + c) * 40 + hh) * 40 + ws) * 4 + j];
        sh[((c * 4 + row) * 42 + wx) * 4 + j] = v;
    }
    __syncthreads();

    {   // conv phase: thread = (r, w, o)
        int r = tid / 320;
        int rt = tid % 320;
        int w = rt % 40, o = rt / 40;
        float wg[18];
#pragma unroll
        for (int i = 0; i < 18; i++) wg[i] = cw[o * 18 + i] * 20.0f;

        float u = 0.f, v = 0.f;
        uint32_t ow[4];
#pragma unroll
        for (int j = 0; j < 4; j++) {
            float acc[32];
#pragma unroll
            for (int k = 0; k < 32; k++) acc[k] = 0.f;
#pragma unroll
            for (int c = 0; c < 2; c++)
#pragma unroll
            for (int dy = 0; dy < 3; dy++)
#pragma unroll
            for (int dx = 0; dx < 3; dx++) {
                uint32_t wd = sh[((c * 4 + (r + dy)) * 42 + (w + dx)) * 4 + j];
                float wt = wg[c * 9 + dy * 3 + dx];
#pragma unroll
                for (int k = 0; k < 32; k++)
                    if (wd & (1u << k)) acc[k] += wt;
            }
            uint32_t bits = 0;
#pragma unroll
            for (int k = 0; k < 32; k++) {
                u = AI * u + acc[k];
                v = AV * v + u;
                if (v >= TH) { bits |= 1u << k; v = 0.f; }
            }
            ow[j] = bits;
        }
        int sdi = ((r * 40 + w) * 8 + o) * 4;
        sd[sdi + 0] = ow[0] << 1;
        sd[sdi + 1] = (ow[1] << 1) | (ow[0] >> 31);
        sd[sdi + 2] = (ow[2] << 1) | (ow[1] >> 31);
        sd[sdi + 3] = (ow[3] << 1) | (ow[2] >> 31);
    }
    __syncthreads();

    if (tid < 160) {   // pool phase
        int pw_ = tid % 20, c = tid / 20;
        float scale = pws[0];
        const uint32_t* p00 = &sd[((0 * 40 + 2 * pw_) * 8 + c) * 4];
        const uint32_t* p01 = &sd[((0 * 40 + 2 * pw_ + 1) * 8 + c) * 4];
        const uint32_t* p10 = &sd[((1 * 40 + 2 * pw_) * 8 + c) * 4];
        const uint32_t* p11 = &sd[((1 * 40 + 2 * pw_ + 1) * 8 + c) * 4];

        float u = 0.f, v = 0.f;
        uint32_t ow[4];
#pragma unroll
        for (int j = 0; j < 4; j++) {
            uint32_t a = p00[j], bb = p01[j], cc = p10[j], d = p11[j];
            uint32_t bits = 0;
#pragma unroll
            for (int k = 0; k < 32; k++) {
                int cnt = (int)((a >> k) & 1u) + (int)((bb >> k) & 1u)
                        + (int)((cc >> k) & 1u) + (int)((d >> k) & 1u);
                float x = (float)cnt * scale;
                u = AI * u + x;
                v = AV * v + u;
                if (v >= TH) { bits |= 1u << k; v = 0.f; }
            }
            ow[j] = bits;
        }
        sp[(c * 20 + pw_) * 4 + 0] = ow[0] << 1;
        sp[(c * 20 + pw_) * 4 + 1] = (ow[1] << 1) | (ow[0] >> 31);
        sp[(c * 20 + pw_) * 4 + 2] = (ow[2] << 1) | (ow[1] >> 31);
        sp[(c * 20 + pw_) * 4 + 3] = (ow[3] << 1) | (ow[2] >> 31);
    }
    __syncthreads();

    if (tid < 80) {    // transpose phase -> g_cp1
        int pw_ = tid >> 2, j = tid & 3;
        uint32_t wc[8];
#pragma unroll
        for (int c = 0; c < 8; c++)
            wc[c] = sp[(c * 20 + pw_) * 4 + j];
        uint8_t* dst = g_cp1 + ((size_t)n * 484 + (ph + 1) * 22 + (pw_ + 1)) * 128 + j * 32;
#pragma unroll
        for (int k = 0; k < 32; k += 4) {
            uint32_t v = 0;
#pragma unroll
            for (int q = 0; q < 4; q++) {
                uint32_t byte = 0;
#pragma unroll
                for (int c = 0; c < 8; c++)
                    byte |= ((wc[c] >> (k + q)) & 1u) << c;
                v |= byte << (q * 8);
            }
            *(uint32_t*)(dst + k) = v;
        }
    }
}

// ---------------------------------------------------------------------------
// K3: sparse conv2 o-quad (R5, proven) -> g_s3
// ---------------------------------------------------------------------------
__global__ void __launch_bounds__(128) k_conv2s(const float* __restrict__ wsrc) {
    __shared__ float4   shW4[72 * 4];
    __shared__ uint32_t shTW[128 * 3];
    __shared__ float    pre[16 * 129];
    int px = blockIdx.x, n = blockIdx.y;
    int h = px / 20, w = px % 20;
    int tid = threadIdx.x;

    for (int i = tid; i < 72 * 4; i += 128) {
        int q = i & 3, tap = i >> 2;
        int c = tap & 7, dydx = tap >> 3;
        float4 v;
        v.x = wsrc[((4 * q + 0) * 8 + c) * 9 + dydx] * 100.0f;
        v.y = wsrc[((4 * q + 1) * 8 + c) * 9 + dydx] * 100.0f;
        v.z = wsrc[((4 * q + 2) * 8 + c) * 9 + dydx] * 100.0f;
        v.w = wsrc[((4 * q + 3) * 8 + c) * 9 + dydx] * 100.0f;
        shW4[i] = v;
    }
    {
        const uint8_t* base = g_cp1 + ((size_t)n * 484 + h * 22 + w) * 128 + tid;
        uint32_t b[9];
#pragma unroll
        for (int dy = 0; dy < 3; dy++)
#pragma unroll
            for (int dx = 0; dx < 3; dx++)
                b[dy * 3 + dx] = base[(dy * 22 + dx) * 128];
        shTW[tid * 3 + 0] = b[0] | (b[1] << 8) | (b[2] << 16) | (b[3] << 24);
        shTW[tid * 3 + 1] = b[4] | (b[5] << 8) | (b[6] << 16) | (b[7] << 24);
        shTW[tid * 3 + 2] = b[8];
    }
    __syncthreads();

    int q = tid & 3, tq = tid >> 2;
#pragma unroll
    for (int i = 0; i < 4; i++) {
        int t = tq * 4 + i;
        uint32_t s0 = shTW[t * 3], s1 = shTW[t * 3 + 1], s2 = shTW[t * 3 + 2];
        unsigned long long a0 = 0ull, a1 = 0ull;
        while (s0) {
            int k = __ffs(s0) - 1; s0 &= s0 - 1;
            const ulonglong2 wv = *(const ulonglong2*)&shW4[k * 4 + q];
            add2(a0, wv.x); add2(a1, wv.y);
        }
        while (s1) {
            int k = __ffs(s1) - 1; s1 &= s1 - 1;
            const ulonglong2 wv = *(const ulonglong2*)&shW4[(32 + k) * 4 + q];
            add2(a0, wv.x); add2(a1, wv.y);
        }
        while (s2) {
            int k = __ffs(s2) - 1; s2 &= s2 - 1;
            const ulonglong2 wv = *(const ulonglong2*)&shW4[(64 + k) * 4 + q];
            add2(a0, wv.x); add2(a1, wv.y);
        }
        float2 f0 = u64f2(a0), f1 = u64f2(a1);
        pre[(4 * q + 0) * 129 + t] = f0.x;
        pre[(4 * q + 1) * 129 + t] = f0.y;
        pre[(4 * q + 2) * 129 + t] = f1.x;
        pre[(4 * q + 3) * 129 + t] = f1.y;
    }
    __syncthreads();

    if (tid < 16) {
        float u = 0.f, v = 0.f;
        uint32_t ow[4];
#pragma unroll
        for (int j = 0; j < 4; j++) {
            uint32_t bits = 0;
#pragma unroll
            for (int k = 0; k < 32; k++) {
                u = AI * u + pre[tid * 129 + j * 32 + k];
                v = AV * v + u;
                if (v >= TH) { bits |= 1u << k; v = 0.f; }
            }
            ow[j] = bits;
        }
        uint32_t d0 = ow[0] << 1;
        uint32_t d1 = (ow[1] << 1) | (ow[0] >> 31);
        uint32_t d2 = (ow[2] << 1) | (ow[1] >> 31);
        uint32_t d3 = (ow[3] << 1) | (ow[2] >> 31);
        *((uint4*)&g_s3[((size_t)((n * 16 + tid) * 400 + px)) * 4]) =
            make_uint4(d0, d1, d2, d3);
    }
}

// ---------------------------------------------------------------------------
// K_p2t: FUSED pool2 + LIF + delay + c-major u16 transpose -> g_cp2 (R14)
// ---------------------------------------------------------------------------
__global__ void __launch_bounds__(160) k_p2t(const float* __restrict__ pws) {
    __shared__ uint32_t sp[16 * 10 * 4];
    int b = blockIdx.x;
    int n = b / 10, ph = b % 10;
    int tid = threadIdx.x;

    {
        int pw_ = tid % 10, c = tid / 10;
        float scale = pws[0];
        const uint32_t* b00 = &g_s3[((size_t)((n * 16 + c) * 400 + (2 * ph) * 20 + 2 * pw_)) * 4];
        const uint32_t* b10 = b00 + 20 * 4;

        float u = 0.f, v = 0.f;
        uint32_t ow[4];
#pragma unroll
        for (int j = 0; j < 4; j++) {
            uint32_t a = b00[j], bb = b00[4 + j], cc = b10[j], d = b10[4 + j];
            uint32_t bits = 0;
#pragma unroll
            for (int k = 0; k < 32; k++) {
                int cnt = (int)((a >> k) & 1u) + (int)((bb >> k) & 1u)
                        + (int)((cc >> k) & 1u) + (int)((d >> k) & 1u);
                float x = (float)cnt * scale;
                u = AI * u + x;
                v = AV * v + u;
                if (v >= TH) { bits |= 1u << k; v = 0.f; }
            }
            ow[j] = bits;
        }
        sp[(c * 10 + pw_) * 4 + 0] = ow[0] << 1;
        sp[(c * 10 + pw_) * 4 + 1] = (ow[1] << 1) | (ow[0] >> 31);
        sp[(c * 10 + pw_) * 4 + 2] = (ow[2] << 1) | (ow[1] >> 31);
        sp[(c * 10 + pw_) * 4 + 3] = (ow[3] << 1) | (ow[2] >> 31);
    }
    __syncthreads();

    if (tid < 40) {
        int pw_ = tid >> 2, j = tid & 3;
        uint32_t wc[16];
#pragma unroll
        for (int c = 0; c < 16; c++)
            wc[c] = sp[(c * 10 + pw_) * 4 + j];
        uint16_t* dst = g_cp2 + ((size_t)n * 144 + (ph + 1) * 12 + (pw_ + 1)) * 128 + j * 32;
#pragma unroll
        for (int k = 0; k < 32; k += 2) {
            uint32_t v = 0;
#pragma unroll
            for (int c = 0; c < 16; c++) {
                v |= ((wc[c] >> k) & 1u) << c;
                v |= ((wc[c] >> (k + 1)) & 1u) << (16 + c);
            }
            *(uint32_t*)(dst + k) = v;
        }
    }
}

// ---------------------------------------------------------------------------
// K5: sparse conv3 o-quad (R5, proven) -> g_s5
// ---------------------------------------------------------------------------
__global__ void __launch_bounds__(128) k_conv3s(const float* __restrict__ wsrc) {
    __shared__ float4   shW4[144 * 8];
    __shared__ uint32_t shTW[128 * 5];
    __shared__ float    pre[32 * 129];
    int px = blockIdx.x, n = blockIdx.y;
    int h = px / 10, w = px % 10;
    int tid = threadIdx.x;

    for (int i = tid; i < 144 * 8; i += 128) {
        int q = i & 7, tap = i >> 3;
        int c = tap & 15, dydx = tap >> 4;
        float4 v;
        v.x = wsrc[((4 * q + 0) * 16 + c) * 9 + dydx] * 100.0f;
        v.y = wsrc[((4 * q + 1) * 16 + c) * 9 + dydx] * 100.0f;
        v.z = wsrc[((4 * q + 2) * 16 + c) * 9 + dydx] * 100.0f;
        v.w = wsrc[((4 * q + 3) * 16 + c) * 9 + dydx] * 100.0f;
        shW4[i] = v;
    }
    {
        const uint16_t* base = g_cp2 + ((size_t)n * 144 + h * 12 + w) * 128 + tid;
        uint32_t b[9];
#pragma unroll
        for (int dy = 0; dy < 3; dy++)
#pragma unroll
            for (int dx = 0; dx < 3; dx++)
                b[dy * 3 + dx] = base[(dy * 12 + dx) * 128];
        shTW[tid * 5 + 0] = b[0] | (b[1] << 16);
        shTW[tid * 5 + 1] = b[2] | (b[3] << 16);
        shTW[tid * 5 + 2] = b[4] | (b[5] << 16);
        shTW[tid * 5 + 3] = b[6] | (b[7] << 16);
        shTW[tid * 5 + 4] = b[8];
    }
    __syncthreads();

    int q = tid & 7, tq = tid >> 3;
#pragma unroll
    for (int i = 0; i < 8; i++) {
        int t = tq * 8 + i;
        unsigned long long a0 = 0ull, a1 = 0ull;
#pragma unroll
        for (int m = 0; m < 5; m++) {
            uint32_t s = shTW[t * 5 + m];
            while (s) {
                int k = __ffs(s) - 1; s &= s - 1;
                const ulonglong2 wv = *(const ulonglong2*)&shW4[(m * 32 + k) * 8 + q];
                add2(a0, wv.x); add2(a1, wv.y);
            }
        }
        float2 f0 = u64f2(a0), f1 = u64f2(a1);
        pre[(4 * q + 0) * 129 + t] = f0.x;
        pre[(4 * q + 1) * 129 + t] = f0.y;
        pre[(4 * q + 2) * 129 + t] = f1.x;
        pre[(4 * q + 3) * 129 + t] = f1.y;
    }
    __syncthreads();

    if (tid < 32) {
        float u = 0.f, v = 0.f;
        uint32_t ow[4];
#pragma unroll
        for (int j = 0; j < 4; j++) {
            uint32_t bits = 0;
#pragma unroll
            for (int k = 0; k < 32; k++) {
                u = AI * u + pre[tid * 129 + j * 32 + k];
                v = AV * v + u;
                if (v >= TH) { bits |= 1u << k; v = 0.f; }
            }
            ow[j] = bits;
        }
        uint32_t d0 = ow[0] << 1;
        uint32_t d1 = (ow[1] << 1) | (ow[0] >> 31);
        uint32_t d2 = (ow[2] << 1) | (ow[1] >> 31);
        uint32_t d3 = (ow[3] << 1) | (ow[2] >> 31);
        *((uint4*)&g_s5[((size_t)(n * 3200 + tid * 100 + px)) * 4]) =
            make_uint4(d0, d1, d2, d3);
    }
}

// ---------------------------------------------------------------------------
// K5b: bit transpose t-major -> c-major (FC input)
// ---------------------------------------------------------------------------
__global__ void k_trans() {
    int gw = (blockIdx.x * blockDim.x + threadIdx.x) >> 5;
    int lane = threadIdx.x & 31;
    int n = gw / 400;
    int r = gw % 400;
    int cw = r >> 2;
    int j = r & 3;
    uint32_t w = g_s5[((size_t)n * 3200 + cw * 32 + lane) * 4 + j];
    uint32_t out = 0;
#pragma unroll
    for (int b = 0; b < 32; b++) {
        uint32_t bl = __ballot_sync(0xffffffffu, (w >> b) & 1u);
        if (lane == b) out = bl;
    }
    g_sb[((size_t)n * 128 + j * 32 + lane) * 100 + cw] = out;
}

// ---------------------------------------------------------------------------
// K_fcw: WMMA bf16 FC (R13/R14). grid (4 ot, 16 n, 2 cs), block 256.
// ---------------------------------------------------------------------------
__global__ void __launch_bounds__(256) k_fcw(float* __restrict__ dp) {
    constexpr int SPLT = 128 * 136;
    extern __shared__ __align__(16) __nv_bfloat16 sm[];
    __nv_bfloat16* sA = sm;              // 3 x [128][136]
    __nv_bfloat16* sB = sm + 3 * SPLT;   // [128][136]

    int ot = blockIdx.x, n = blockIdx.y, cs = blockIdx.z;
    int tid = threadIdx.x;
    int warp = tid >> 5;
    int wy = warp >> 2, wx = warp & 3;

    int cbeg = cs ? 13 : 0;
    int cend = cs ? 25 : 13;

    wmma::fragment<wmma::accumulator, 16, 16, 16, float> acc[4][2];
#pragma unroll
    for (int i = 0; i < 4; i++)
#pragma unroll
        for (int j = 0; j < 2; j++)
            wmma::fill_fragment(acc[i][j], 0.0f);

    for (int cc = cbeg; cc < cend; cc++) {
        __syncthreads();
        {
            int t = tid >> 1, half = tid & 1;
            const uint32_t* src = g_sb + ((size_t)n * 128 + t) * 100 + cc * 4 + half * 2;
            uint32_t w0 = src[0], w1 = src[1];
            uint32_t* d32 = (uint32_t*)(sB + t * 136 + half * 64);
#pragma unroll
            for (int b = 0; b < 16; b++)
                d32[b] = (((w0 >> (2 * b)) & 1u) ? 0x3F80u : 0u)
                       | (((w0 >> (2 * b + 1)) & 1u) ? 0x3F800000u : 0u);
#pragma unroll
            for (int b = 0; b < 16; b++)
                d32[16 + b] = (((w1 >> (2 * b)) & 1u) ? 0x3F80u : 0u)
                            | (((w1 >> (2 * b + 1)) & 1u) ? 0x3F800000u : 0u);
        }
#pragma unroll
        for (int s = 0; s < 3; s++) {
            const uint4* src = (const uint4*)
                (g_wh + ((size_t)s * 512 + ot * 128) * 3200 + cc * 128);
#pragma unroll
            for (int r8 = 0; r8 < 8; r8++) {
                int i = tid + r8 * 256;
                int r = i >> 4, q2 = i & 15;
                uint4 v = src[(size_t)r * 400 + q2];
                *(uint4*)&sA[s * SPLT + r * 136 + q2 * 8] = v;
            }
        }
        __syncthreads();

        for (int s = 0; s < 3; s++) {
#pragma unroll
            for (int k8 = 0; k8 < 8; k8++) {
                wmma::fragment<wmma::matrix_a, 16, 16, 16, __nv_bfloat16,
                               wmma::row_major> af[4];
                wmma::fragment<wmma::matrix_b, 16, 16, 16, __nv_bfloat16,
                               wmma::col_major> bf[2];
#pragma unroll
                for (int i = 0; i < 4; i++)
                    wmma::load_matrix_sync(af[i],
                        sA + s * SPLT + (wy * 64 + i * 16) * 136 + k8 * 16, 136);
#pragma unroll
                for (int j = 0; j < 2; j++)
                    wmma::load_matrix_sync(bf[j],
                        sB + (wx * 32 + j * 16) * 136 + k8 * 16, 136);
#pragma unroll
                for (int i = 0; i < 4; i++)
#pragma unroll
                    for (int j = 0; j < 2; j++)
                        wmma::mma_sync(acc[i][j], af[i], bf[j], acc[i][j]);
            }
        }
    }

    float* base = dp + ((size_t)(cs * 16 + n) * 512 + ot * 128) * 128;
#pragma unroll
    for (int i = 0; i < 4; i++)
#pragma unroll
        for (int j = 0; j < 2; j++)
            wmma::store_matrix_sync(
                base + (wy * 64 + i * 16) * 128 + wx * 32 + j * 16,
                acc[i][j], 128, wmma::mem_row_major);
}

// ---------------------------------------------------------------------------
// K_lif2: sum 2 partials + LIF + output delay-shift -> d_out
// ---------------------------------------------------------------------------
__global__ void k_lif2(float* __restrict__ out) {
    const size_t S = (size_t)16 * 512 * 128;
    int idx = blockIdx.x * blockDim.x + threadIdx.x;
    const float* a = &g_dp2[(size_t)idx * 128];
    float* op = &out[(size_t)idx * 128];
    float u = 0.f, v = 0.f, prev = 0.f;
#pragma unroll 8
    for (int t = 0; t < 128; t++) {
        op[t] = prev;
        float x = a[t] + a[t + S];
        u = AI * u + x;
        v = AV * v + u;
        if (v >= TH) { prev = 1.f; v = 0.f; } else { prev = 0.f; }
    }
}

// ---------------------------------------------------------------------------
extern "C" void kernel_launch(void* const* d_in, const int* in_sizes, int n_in,
                              void* d_out, int out_size) {
    const float* spike = (const float*)d_in[0];
    const float* c1w   = (const float*)d_in[1];
    const float* c2w   = (const float*)d_in[2];
    const float* c3w   = (const float*)d_in[3];
    const float* p1w   = (const float*)d_in[4];
    const float* p2w   = (const float*)d_in[5];
    const float* fcw   = (const float*)d_in[6];
    float* out = (float*)d_out;

    float* dp;
    cudaGetSymbolAddress((void**)&dp, g_dp2);

    const int FCW_SMEM = 4 * 128 * 136 * 2;   // 139264 B
    cudaFuncSetAttribute((const void*)k_fcw,
                         cudaFuncAttributeMaxDynamicSharedMemorySize, FCW_SMEM);

    k_pw<<<3400, 256>>>(spike, fcw);                   // pack + W-split, merged
    k_c1p<<<320, 640>>>(c1w, p1w);                     // conv1+pool1+tr -> g_cp1
    k_conv2s<<<dim3(400, 16), 128>>>(c2w);             // -> g_s3
    k_p2t<<<160, 160>>>(p2w);                          // pool2+tr -> g_cp2
    k_conv3s<<<dim3(100, 16), 128>>>(c3w);             // -> g_s5
    k_trans<<<800, 256>>>();                           // -> g_sb
    k_fcw<<<dim3(4, 16, 2), 256, FCW_SMEM>>>(dp);      // WMMA bf16 FC
    k_lif2<<<32, 256>>>(out);
}